// round 6
// baseline (speedup 1.0000x reference)
#include <cuda_runtime.h>
#include <cuda_bf16.h>

#define IN_F 128
#define HID 128
#define NCTX 32
#define ALPHA 0.2f
#define NEG_INF -9000000000000000.0f
#define MAXN 20000

// Scratch (device globals — no allocation allowed)
__device__ __align__(16) float g_u_i[IN_F];       // W_i @ a_i
__device__ __align__(16) float g_u_j[IN_F];       // W_j @ a_j
__device__ float g_bias;
__device__ float g_s_i[MAXN];
__device__ float g_s_j[MAXN];
__device__ __align__(16) float g_feat[(size_t)MAXN * HID]; // attn-weighted raw-feature sums

// packed f32x2 helpers (Blackwell FFMA2 via PTX)
__device__ __forceinline__ unsigned long long dup2(float a) {
    unsigned long long r;
    asm("mov.b64 %0, {%1, %1};" : "=l"(r) : "f"(a));
    return r;
}
__device__ __forceinline__ void fma2(unsigned long long& d,
                                     unsigned long long a, unsigned long long b) {
    asm("fma.rn.f32x2 %0, %1, %2, %0;" : "+l"(d) : "l"(a), "l"(b));
}
__device__ __forceinline__ void unpk2(unsigned long long v, float& x, float& y) {
    asm("mov.b64 {%0, %1}, %2;" : "=f"(x), "=f"(y) : "l"(v));
}

// ---------------------------------------------------------------------------
// K1: fold attention vectors through weights — one warp per output element.
// ---------------------------------------------------------------------------
__global__ void prep_kernel(const float* __restrict__ W_i,
                            const float* __restrict__ W_j,
                            const float* __restrict__ a_w,
                            const float* __restrict__ a_b) {
    int warp = blockIdx.x * (blockDim.x >> 5) + (threadIdx.x >> 5);  // 0..255
    int lane = threadIdx.x & 31;
    const float* W  = (warp < 128) ? W_i : W_j;
    const float* av = (warp < 128) ? a_w : a_w + HID;
    int f = warp & 127;
    float4 w4 = ((const float4*)W)[f * 32 + lane];
    float4 a4 = ((const float4*)av)[lane];
    float s = w4.x * a4.x + w4.y * a4.y + w4.z * a4.z + w4.w * a4.w;
    #pragma unroll
    for (int o = 16; o; o >>= 1) s += __shfl_xor_sync(0xffffffffu, s, o);
    if (lane == 0) {
        if (warp < 128) g_u_i[f] = s; else g_u_j[f] = s;
    }
    if (warp == 0 && lane == 0) g_bias = a_b[0];
}

// ---------------------------------------------------------------------------
// K2: per-node scalar scores.  s_i[n] = h[n].u_i ; s_j[n] = h[n].u_j
// ---------------------------------------------------------------------------
__global__ void score_kernel(const float* __restrict__ h_i, int N) {
    int warp = blockIdx.x * (blockDim.x >> 5) + (threadIdx.x >> 5);
    int lane = threadIdx.x & 31;
    if (warp >= N) return;
    const float4* h4 = (const float4*)h_i;
    float4 v  = h4[(size_t)warp * 32 + lane];
    float4 ui = ((const float4*)g_u_i)[lane];
    float4 uj = ((const float4*)g_u_j)[lane];
    float a = v.x * ui.x + v.y * ui.y + v.z * ui.z + v.w * ui.w;
    float b = v.x * uj.x + v.y * uj.y + v.z * uj.z + v.w * uj.w;
    #pragma unroll
    for (int o = 16; o; o >>= 1) {
        a += __shfl_xor_sync(0xffffffffu, a, o);
        b += __shfl_xor_sync(0xffffffffu, b, o);
    }
    if (lane == 0) {
        g_s_i[warp] = a;
        g_s_j[warp] = b;
    }
}

// ---------------------------------------------------------------------------
// K3: gather + leaky-relu + softmax + attention-weighted raw-feature sum.
// One warp per node.
// ---------------------------------------------------------------------------
__global__ void gather_kernel(const float* __restrict__ h_i,
                              const int* __restrict__ ctx, int N) {
    int warp = blockIdx.x * (blockDim.x >> 5) + (threadIdx.x >> 5);
    int lane = threadIdx.x & 31;
    if (warp >= N) return;

    int j = ctx[(size_t)warp * NCTX + lane];
    bool valid = (j >= 0);

    float sj = valid ? g_s_j[j] : 0.f;
    float e = g_s_i[warp] + sj + g_bias;
    e = (e > 0.f) ? e : ALPHA * e;       // leaky relu
    e = valid ? e : NEG_INF;             // mask

    float m = e;
    #pragma unroll
    for (int o = 16; o; o >>= 1) m = fmaxf(m, __shfl_xor_sync(0xffffffffu, m, o));
    float p = valid ? __expf(e - m) : 0.f;
    float s = p;
    #pragma unroll
    for (int o = 16; o; o >>= 1) s += __shfl_xor_sync(0xffffffffu, s, o);
    float w = p * ((s > 0.f) ? (1.f / s) : 0.f);

    float4 acc = make_float4(0.f, 0.f, 0.f, 0.f);
    const float4* h4 = (const float4*)h_i;
    #pragma unroll
    for (int c = 0; c < NCTX; c++) {
        float wc = __shfl_sync(0xffffffffu, w, c);
        int jc   = __shfl_sync(0xffffffffu, j, c);
        if (jc >= 0) {
            float4 v = h4[(size_t)jc * 32 + lane];
            acc.x = fmaf(wc, v.x, acc.x);
            acc.y = fmaf(wc, v.y, acc.y);
            acc.z = fmaf(wc, v.z, acc.z);
            acc.w = fmaf(wc, v.w, acc.w);
        }
    }
    ((float4*)g_feat)[(size_t)warp * 32 + lane] = acc;
}

// ---------------------------------------------------------------------------
// K4: out = g_feat @ W_j.  32x128 tile (grid ~625 -> ~4 blocks/SM), 128 thr,
// 4x8 micro-tile with FFMA2.  acc packs column pairs; b operands come straight
// out of LDS.128.  smem 20KB, ~70 regs.
// ---------------------------------------------------------------------------
__global__ __launch_bounds__(128) void out_gemm_kernel(
    const float* __restrict__ Wj, float* __restrict__ out, int N) {
    __shared__ float ws[32][128];   // W k-chunk   (16KB)
    __shared__ float gs[32][32];    // A k-chunk   (4KB)

    int row0 = blockIdx.x * 32;
    int tid  = threadIdx.x;
    int rg   = tid >> 4;     // 0..7  -> rows [rg*4, rg*4+4)
    int cg   = tid & 15;     // 0..15 -> cols [cg*8, cg*8+8)

    unsigned long long acc[4][4];
    #pragma unroll
    for (int r = 0; r < 4; r++)
        #pragma unroll
        for (int q = 0; q < 4; q++) acc[r][q] = 0ull;

    const float4* g4 = (const float4*)g_feat;
    const float4* w4 = (const float4*)Wj;

    for (int k0 = 0; k0 < 128; k0 += 32) {
        __syncthreads();
        // W chunk [k0..k0+32) x 128  (1024 float4 / 128 thr = 8 each)
        #pragma unroll
        for (int i = tid; i < 32 * 32; i += 128) {
            int r = i >> 5, c4 = i & 31;
            ((float4*)&ws[r][0])[c4] = w4[(size_t)(k0 + r) * 32 + c4];
        }
        // A chunk rows [row0..row0+32) x k [k0..k0+32)  (256 float4 / 128 = 2 each)
        #pragma unroll
        for (int i = tid; i < 32 * 8; i += 128) {
            int r = i >> 3, q = i & 7;
            int gr = row0 + r;
            float4 v = make_float4(0.f, 0.f, 0.f, 0.f);
            if (gr < N) v = g4[(size_t)gr * 32 + (k0 >> 2) + q];
            ((float4*)&gs[r][0])[q] = v;
        }
        __syncthreads();

        #pragma unroll
        for (int kk = 0; kk < 32; kk++) {
            float4 b0 = *(const float4*)&ws[kk][cg * 8];
            float4 b1 = *(const float4*)&ws[kk][cg * 8 + 4];
            unsigned long long bv0 = *(const unsigned long long*)&b0.x;
            unsigned long long bv1 = *(const unsigned long long*)&b0.z;
            unsigned long long bv2 = *(const unsigned long long*)&b1.x;
            unsigned long long bv3 = *(const unsigned long long*)&b1.z;
            #pragma unroll
            for (int r = 0; r < 4; r++) {
                unsigned long long av = dup2(gs[rg * 4 + r][kk]);
                fma2(acc[r][0], av, bv0);
                fma2(acc[r][1], av, bv1);
                fma2(acc[r][2], av, bv2);
                fma2(acc[r][3], av, bv3);
            }
        }
    }

    #pragma unroll
    for (int r = 0; r < 4; r++) {
        int gr = row0 + rg * 4 + r;
        if (gr < N) {
            float4 o0, o1;
            unpk2(acc[r][0], o0.x, o0.y);
            unpk2(acc[r][1], o0.z, o0.w);
            unpk2(acc[r][2], o1.x, o1.y);
            unpk2(acc[r][3], o1.z, o1.w);
            *(float4*)&out[(size_t)gr * 128 + cg * 8]     = o0;
            *(float4*)&out[(size_t)gr * 128 + cg * 8 + 4] = o1;
        }
    }
}

// ---------------------------------------------------------------------------
extern "C" void kernel_launch(void* const* d_in, const int* in_sizes, int n_in,
                              void* d_out, int out_size) {
    const float* h_i = (const float*)d_in[0];
    const int*   ctx = (const int*)d_in[1];     // int32
    const float* W_i = (const float*)d_in[2];
    const float* W_j = (const float*)d_in[3];
    const float* a_w = (const float*)d_in[4];
    const float* a_b = (const float*)d_in[5];
    float* out = (float*)d_out;

    int N = in_sizes[0] / IN_F;

    prep_kernel<<<32, 256>>>(W_i, W_j, a_w, a_b);

    int blocks = (N + 7) / 8;
    score_kernel<<<blocks, 256>>>(h_i, N);
    gather_kernel<<<blocks, 256>>>(h_i, ctx, N);

    int gemm_blocks = (N + 31) / 32;
    out_gemm_kernel<<<gemm_blocks, 128>>>(W_j, out, N);
}

// round 7
// speedup vs baseline: 1.0066x; 1.0066x over previous
#include <cuda_runtime.h>
#include <cuda_bf16.h>

#define IN_F 128
#define HID 128
#define NCTX 32
#define ALPHA 0.2f
#define NEG_INF -9000000000000000.0f
#define MAXN 20000

// Scratch (device globals — no allocation allowed)
__device__ __align__(16) float g_u_i[IN_F];       // W_i @ a_i
__device__ __align__(16) float g_u_j[IN_F];       // W_j @ a_j
__device__ float g_bias;
__device__ float g_s_i[MAXN];
__device__ float g_s_j[MAXN];
__device__ __align__(16) float g_feat[(size_t)MAXN * HID]; // attn-weighted raw-feature sums

// packed f32x2 helpers (Blackwell FFMA2 via PTX)
__device__ __forceinline__ unsigned long long dup2(float a) {
    unsigned long long r;
    asm("mov.b64 %0, {%1, %1};" : "=l"(r) : "f"(a));
    return r;
}
__device__ __forceinline__ void fma2(unsigned long long& d,
                                     unsigned long long a, unsigned long long b) {
    asm("fma.rn.f32x2 %0, %1, %2, %0;" : "+l"(d) : "l"(a), "l"(b));
}
__device__ __forceinline__ void unpk2(unsigned long long v, float& x, float& y) {
    asm("mov.b64 {%0, %1}, %2;" : "=f"(x), "=f"(y) : "l"(v));
}

// ---------------------------------------------------------------------------
// K1: fold attention vectors through weights — one warp per output element.
// ---------------------------------------------------------------------------
__global__ void prep_kernel(const float* __restrict__ W_i,
                            const float* __restrict__ W_j,
                            const float* __restrict__ a_w,
                            const float* __restrict__ a_b) {
    int warp = blockIdx.x * (blockDim.x >> 5) + (threadIdx.x >> 5);  // 0..255
    int lane = threadIdx.x & 31;
    const float* W  = (warp < 128) ? W_i : W_j;
    const float* av = (warp < 128) ? a_w : a_w + HID;
    int f = warp & 127;
    float4 w4 = ((const float4*)W)[f * 32 + lane];
    float4 a4 = ((const float4*)av)[lane];
    float s = w4.x * a4.x + w4.y * a4.y + w4.z * a4.z + w4.w * a4.w;
    #pragma unroll
    for (int o = 16; o; o >>= 1) s += __shfl_xor_sync(0xffffffffu, s, o);
    if (lane == 0) {
        if (warp < 128) g_u_i[f] = s; else g_u_j[f] = s;
    }
    if (warp == 0 && lane == 0) g_bias = a_b[0];
}

// ---------------------------------------------------------------------------
// K2: per-node scalar scores.  s_i[n] = h[n].u_i ; s_j[n] = h[n].u_j
// ---------------------------------------------------------------------------
__global__ void score_kernel(const float* __restrict__ h_i, int N) {
    int warp = blockIdx.x * (blockDim.x >> 5) + (threadIdx.x >> 5);
    int lane = threadIdx.x & 31;
    if (warp >= N) return;
    const float4* h4 = (const float4*)h_i;
    float4 v  = h4[(size_t)warp * 32 + lane];
    float4 ui = ((const float4*)g_u_i)[lane];
    float4 uj = ((const float4*)g_u_j)[lane];
    float a = v.x * ui.x + v.y * ui.y + v.z * ui.z + v.w * ui.w;
    float b = v.x * uj.x + v.y * uj.y + v.z * uj.z + v.w * uj.w;
    #pragma unroll
    for (int o = 16; o; o >>= 1) {
        a += __shfl_xor_sync(0xffffffffu, a, o);
        b += __shfl_xor_sync(0xffffffffu, b, o);
    }
    if (lane == 0) {
        g_s_i[warp] = a;
        g_s_j[warp] = b;
    }
}

// ---------------------------------------------------------------------------
// K3: gather + leaky-relu + softmax + attention-weighted raw-feature sum.
// One warp per node.
// ---------------------------------------------------------------------------
__global__ void gather_kernel(const float* __restrict__ h_i,
                              const int* __restrict__ ctx, int N) {
    int warp = blockIdx.x * (blockDim.x >> 5) + (threadIdx.x >> 5);
    int lane = threadIdx.x & 31;
    if (warp >= N) return;

    int j = ctx[(size_t)warp * NCTX + lane];
    bool valid = (j >= 0);

    float sj = valid ? g_s_j[j] : 0.f;
    float e = g_s_i[warp] + sj + g_bias;
    e = (e > 0.f) ? e : ALPHA * e;       // leaky relu
    e = valid ? e : NEG_INF;             // mask

    float m = e;
    #pragma unroll
    for (int o = 16; o; o >>= 1) m = fmaxf(m, __shfl_xor_sync(0xffffffffu, m, o));
    float p = valid ? __expf(e - m) : 0.f;
    float s = p;
    #pragma unroll
    for (int o = 16; o; o >>= 1) s += __shfl_xor_sync(0xffffffffu, s, o);
    float w = p * ((s > 0.f) ? (1.f / s) : 0.f);

    float4 acc = make_float4(0.f, 0.f, 0.f, 0.f);
    const float4* h4 = (const float4*)h_i;
    #pragma unroll
    for (int c = 0; c < NCTX; c++) {
        float wc = __shfl_sync(0xffffffffu, w, c);
        int jc   = __shfl_sync(0xffffffffu, j, c);
        if (jc >= 0) {
            float4 v = h4[(size_t)jc * 32 + lane];
            acc.x = fmaf(wc, v.x, acc.x);
            acc.y = fmaf(wc, v.y, acc.y);
            acc.z = fmaf(wc, v.z, acc.z);
            acc.w = fmaf(wc, v.w, acc.w);
        }
    }
    ((float4*)g_feat)[(size_t)warp * 32 + lane] = acc;
}

// ---------------------------------------------------------------------------
// K4 (v5): out = g_feat @ W_j.  Tile 32 rows x 64 cols, 64 threads,
// micro-tile 4x8 with FFMA2.  2D grid (row tiles x 2 col-halves) ->
// 1250 blocks, ~17 warps/SM.  Crossbar-balanced:
//   b: 2x LDS.128, 4-way lane-dedup -> 1 cyc each
//   a: broadcast LDS.32, gs stride 33 -> conflict-free
// ---------------------------------------------------------------------------
__global__ __launch_bounds__(64) void out_gemm_kernel(
    const float* __restrict__ Wj, float* __restrict__ out, int N) {
    __shared__ float ws[32][64];    // W k-chunk x 64-col half (8KB)
    __shared__ float gs[32][33];    // A rows x k-chunk, padded (4.2KB)

    int row0 = blockIdx.x * 32;
    int col0 = blockIdx.y * 64;
    int tid  = threadIdx.x;
    int rg   = tid >> 3;     // 0..7 -> rows [rg*4, rg*4+4)
    int cg   = tid & 7;      // 0..7 -> cols [cg*8, cg*8+8)

    unsigned long long acc[4][4];
    #pragma unroll
    for (int r = 0; r < 4; r++)
        #pragma unroll
        for (int q = 0; q < 4; q++) acc[r][q] = 0ull;

    const float4* g4 = (const float4*)g_feat;
    const float4* w4 = (const float4*)Wj;

    for (int k0 = 0; k0 < 128; k0 += 32) {
        __syncthreads();
        // W chunk [k0..k0+32) x cols [col0..col0+64)  (512 float4 / 64 thr)
        #pragma unroll
        for (int i = tid; i < 32 * 16; i += 64) {
            int r = i >> 4, c4 = i & 15;
            ((float4*)&ws[r][0])[c4] = w4[(size_t)(k0 + r) * 32 + (col0 >> 2) + c4];
        }
        // A chunk rows [row0..row0+32) x k [k0..k0+32), scalar STS (stride 33)
        #pragma unroll
        for (int i = tid; i < 32 * 8; i += 64) {
            int r = i >> 3, q = i & 7;
            int gr = row0 + r;
            float4 v = make_float4(0.f, 0.f, 0.f, 0.f);
            if (gr < N) v = g4[(size_t)gr * 32 + (k0 >> 2) + q];
            gs[r][q * 4 + 0] = v.x;
            gs[r][q * 4 + 1] = v.y;
            gs[r][q * 4 + 2] = v.z;
            gs[r][q * 4 + 3] = v.w;
        }
        __syncthreads();

        #pragma unroll
        for (int kk = 0; kk < 32; kk++) {
            float4 b0 = *(const float4*)&ws[kk][cg * 8];
            float4 b1 = *(const float4*)&ws[kk][cg * 8 + 4];
            unsigned long long bv0 = *(const unsigned long long*)&b0.x;
            unsigned long long bv1 = *(const unsigned long long*)&b0.z;
            unsigned long long bv2 = *(const unsigned long long*)&b1.x;
            unsigned long long bv3 = *(const unsigned long long*)&b1.z;
            #pragma unroll
            for (int r = 0; r < 4; r++) {
                unsigned long long av = dup2(gs[rg * 4 + r][kk]);
                fma2(acc[r][0], av, bv0);
                fma2(acc[r][1], av, bv1);
                fma2(acc[r][2], av, bv2);
                fma2(acc[r][3], av, bv3);
            }
        }
    }

    #pragma unroll
    for (int r = 0; r < 4; r++) {
        int gr = row0 + rg * 4 + r;
        if (gr < N) {
            float4 o0, o1;
            unpk2(acc[r][0], o0.x, o0.y);
            unpk2(acc[r][1], o0.z, o0.w);
            unpk2(acc[r][2], o1.x, o1.y);
            unpk2(acc[r][3], o1.z, o1.w);
            *(float4*)&out[(size_t)gr * 128 + col0 + cg * 8]     = o0;
            *(float4*)&out[(size_t)gr * 128 + col0 + cg * 8 + 4] = o1;
        }
    }
}

// ---------------------------------------------------------------------------
extern "C" void kernel_launch(void* const* d_in, const int* in_sizes, int n_in,
                              void* d_out, int out_size) {
    const float* h_i = (const float*)d_in[0];
    const int*   ctx = (const int*)d_in[1];     // int32
    const float* W_i = (const float*)d_in[2];
    const float* W_j = (const float*)d_in[3];
    const float* a_w = (const float*)d_in[4];
    const float* a_b = (const float*)d_in[5];
    float* out = (float*)d_out;

    int N = in_sizes[0] / IN_F;

    prep_kernel<<<32, 256>>>(W_i, W_j, a_w, a_b);

    int blocks = (N + 7) / 8;
    score_kernel<<<blocks, 256>>>(h_i, N);
    gather_kernel<<<blocks, 256>>>(h_i, ctx, N);

    dim3 ggrid((N + 31) / 32, 2);
    out_gemm_kernel<<<ggrid, 64>>>(W_j, out, N);
}

// round 8
// speedup vs baseline: 1.0442x; 1.0373x over previous
#include <cuda_runtime.h>
#include <cuda_bf16.h>

#define IN_F 128
#define HID 128
#define NCTX 32
#define ALPHA 0.2f
#define NEG_INF -9000000000000000.0f
#define MAXN 20000

// Scratch (device globals — no allocation allowed)
__device__ __align__(16) float g_u_i[IN_F];       // W_i @ a_i
__device__ __align__(16) float g_u_j[IN_F];       // W_j @ a_j
__device__ float g_bias;
__device__ float g_s_i[MAXN];
__device__ float g_s_j[MAXN];
__device__ __align__(16) float g_feat[(size_t)MAXN * HID]; // attn-weighted raw-feature sums

// packed f32x2 helpers (Blackwell FFMA2 via PTX)
__device__ __forceinline__ unsigned long long dup2(float a) {
    unsigned long long r;
    asm("mov.b64 %0, {%1, %1};" : "=l"(r) : "f"(a));
    return r;
}
__device__ __forceinline__ void fma2(unsigned long long& d,
                                     unsigned long long a, unsigned long long b) {
    asm("fma.rn.f32x2 %0, %1, %2, %0;" : "+l"(d) : "l"(a), "l"(b));
}
__device__ __forceinline__ void unpk2(unsigned long long v, float& x, float& y) {
    asm("mov.b64 {%0, %1}, %2;" : "=f"(x), "=f"(y) : "l"(v));
}

// ---------------------------------------------------------------------------
// K1: fold attention vectors through weights — one warp per output element.
// ---------------------------------------------------------------------------
__global__ void prep_kernel(const float* __restrict__ W_i,
                            const float* __restrict__ W_j,
                            const float* __restrict__ a_w,
                            const float* __restrict__ a_b) {
    int warp = blockIdx.x * (blockDim.x >> 5) + (threadIdx.x >> 5);  // 0..255
    int lane = threadIdx.x & 31;
    const float* W  = (warp < 128) ? W_i : W_j;
    const float* av = (warp < 128) ? a_w : a_w + HID;
    int f = warp & 127;
    float4 w4 = ((const float4*)W)[f * 32 + lane];
    float4 a4 = ((const float4*)av)[lane];
    float s = w4.x * a4.x + w4.y * a4.y + w4.z * a4.z + w4.w * a4.w;
    #pragma unroll
    for (int o = 16; o; o >>= 1) s += __shfl_xor_sync(0xffffffffu, s, o);
    if (lane == 0) {
        if (warp < 128) g_u_i[f] = s; else g_u_j[f] = s;
    }
    if (warp == 0 && lane == 0) g_bias = a_b[0];
}

// ---------------------------------------------------------------------------
// K2: per-node scalar scores.  s_i[n] = h[n].u_i ; s_j[n] = h[n].u_j
// ---------------------------------------------------------------------------
__global__ void score_kernel(const float* __restrict__ h_i, int N) {
    int warp = blockIdx.x * (blockDim.x >> 5) + (threadIdx.x >> 5);
    int lane = threadIdx.x & 31;
    if (warp >= N) return;
    const float4* h4 = (const float4*)h_i;
    float4 v  = h4[(size_t)warp * 32 + lane];
    float4 ui = ((const float4*)g_u_i)[lane];
    float4 uj = ((const float4*)g_u_j)[lane];
    float a = v.x * ui.x + v.y * ui.y + v.z * ui.z + v.w * ui.w;
    float b = v.x * uj.x + v.y * uj.y + v.z * uj.z + v.w * uj.w;
    #pragma unroll
    for (int o = 16; o; o >>= 1) {
        a += __shfl_xor_sync(0xffffffffu, a, o);
        b += __shfl_xor_sync(0xffffffffu, b, o);
    }
    if (lane == 0) {
        g_s_i[warp] = a;
        g_s_j[warp] = b;
    }
}

// ---------------------------------------------------------------------------
// K3: gather + leaky-relu + softmax + attention-weighted raw-feature sum.
// One warp per node.
// ---------------------------------------------------------------------------
__global__ void gather_kernel(const float* __restrict__ h_i,
                              const int* __restrict__ ctx, int N) {
    int warp = blockIdx.x * (blockDim.x >> 5) + (threadIdx.x >> 5);
    int lane = threadIdx.x & 31;
    if (warp >= N) return;

    int j = ctx[(size_t)warp * NCTX + lane];
    bool valid = (j >= 0);

    float sj = valid ? g_s_j[j] : 0.f;
    float e = g_s_i[warp] + sj + g_bias;
    e = (e > 0.f) ? e : ALPHA * e;       // leaky relu
    e = valid ? e : NEG_INF;             // mask

    float m = e;
    #pragma unroll
    for (int o = 16; o; o >>= 1) m = fmaxf(m, __shfl_xor_sync(0xffffffffu, m, o));
    float p = valid ? __expf(e - m) : 0.f;
    float s = p;
    #pragma unroll
    for (int o = 16; o; o >>= 1) s += __shfl_xor_sync(0xffffffffu, s, o);
    float w = p * ((s > 0.f) ? (1.f / s) : 0.f);

    float4 acc = make_float4(0.f, 0.f, 0.f, 0.f);
    const float4* h4 = (const float4*)h_i;
    #pragma unroll
    for (int c = 0; c < NCTX; c++) {
        float wc = __shfl_sync(0xffffffffu, w, c);
        int jc   = __shfl_sync(0xffffffffu, j, c);
        if (jc >= 0) {
            float4 v = h4[(size_t)jc * 32 + lane];
            acc.x = fmaf(wc, v.x, acc.x);
            acc.y = fmaf(wc, v.y, acc.y);
            acc.z = fmaf(wc, v.z, acc.z);
            acc.w = fmaf(wc, v.w, acc.w);
        }
    }
    ((float4*)g_feat)[(size_t)warp * 32 + lane] = acc;
}

// ---------------------------------------------------------------------------
// K4 (v6): out = g_feat @ W_j.  256 thr / 8 warps / 32 rows per block.
// Warp owns 4 rows x 128 cols; lane owns cols [lane*4, lane*4+4).
// Inner loop per k:  1x LDS.128 (b, 4 distinct cols/lane)
//                  + 4x broadcast LDS.64 of PRE-DUPLICATED {a,a} pairs (1cyc,
//                    no dup2 mov)  + 8x FFMA2.
// 13 issue slots / 8 crossbar-cyc / 16 fma-cyc per kk -> FMA-bound.
// smem 48KB, ~48 regs -> 4 blocks/SM (32 warps).  grid = 625.
// ---------------------------------------------------------------------------
__global__ __launch_bounds__(256, 4) void out_gemm_kernel(
    const float* __restrict__ Wj, float* __restrict__ out, int N) {
    __shared__ float ws[32][128];                       // W k-chunk (16KB)
    __shared__ unsigned long long adup[32][128];        // {a,a} pairs (32KB)

    int row0 = blockIdx.x * 32;
    int tid  = threadIdx.x;
    int warp = tid >> 5;
    int lane = tid & 31;

    const float4* g4  = (const float4*)g_feat;
    const float4* w4p = (const float4*)Wj;

    // Fill adup once: rows [row0..row0+32) x k [0..128), duplicated f32x2.
    #pragma unroll
    for (int idx = tid; idx < 32 * 32; idx += 256) {
        int r = idx >> 5, q = idx & 31;
        int gr = row0 + r;
        float4 v = make_float4(0.f, 0.f, 0.f, 0.f);
        if (gr < N) v = g4[(size_t)gr * 32 + q];
        adup[r][q * 4 + 0] = dup2(v.x);
        adup[r][q * 4 + 1] = dup2(v.y);
        adup[r][q * 4 + 2] = dup2(v.z);
        adup[r][q * 4 + 3] = dup2(v.w);
    }

    unsigned long long acc[4][2];
    #pragma unroll
    for (int r = 0; r < 4; r++) { acc[r][0] = 0ull; acc[r][1] = 0ull; }

    for (int kc = 0; kc < 4; kc++) {
        __syncthreads();   // kc=0: covers adup fill; kc>0: drains ws readers
        #pragma unroll
        for (int i = tid; i < 32 * 32; i += 256) {
            int r = i >> 5, c4 = i & 31;
            ((float4*)&ws[r][0])[c4] = w4p[(size_t)(kc * 32 + r) * 32 + c4];
        }
        __syncthreads();

        #pragma unroll
        for (int kk = 0; kk < 32; kk++) {
            float4 w = *(const float4*)&ws[kk][lane * 4];
            unsigned long long wlo = *(const unsigned long long*)&w.x;
            unsigned long long whi = *(const unsigned long long*)&w.z;
            #pragma unroll
            for (int r = 0; r < 4; r++) {
                unsigned long long av = adup[warp * 4 + r][kc * 32 + kk]; // broadcast
                fma2(acc[r][0], av, wlo);
                fma2(acc[r][1], av, whi);
            }
        }
    }

    #pragma unroll
    for (int r = 0; r < 4; r++) {
        int gr = row0 + warp * 4 + r;
        if (gr < N) {
            float4 o;
            unpk2(acc[r][0], o.x, o.y);
            unpk2(acc[r][1], o.z, o.w);
            *(float4*)&out[(size_t)gr * 128 + lane * 4] = o;
        }
    }
}

// ---------------------------------------------------------------------------
extern "C" void kernel_launch(void* const* d_in, const int* in_sizes, int n_in,
                              void* d_out, int out_size) {
    const float* h_i = (const float*)d_in[0];
    const int*   ctx = (const int*)d_in[1];     // int32
    const float* W_i = (const float*)d_in[2];
    const float* W_j = (const float*)d_in[3];
    const float* a_w = (const float*)d_in[4];
    const float* a_b = (const float*)d_in[5];
    float* out = (float*)d_out;

    int N = in_sizes[0] / IN_F;

    prep_kernel<<<32, 256>>>(W_i, W_j, a_w, a_b);

    int blocks = (N + 7) / 8;
    score_kernel<<<blocks, 256>>>(h_i, N);
    gather_kernel<<<blocks, 256>>>(h_i, ctx, N);

    int gemm_blocks = (N + 31) / 32;
    out_gemm_kernel<<<gemm_blocks, 256>>>(W_j, out, N);
}